// round 6
// baseline (speedup 1.0000x reference)
#include <cuda_runtime.h>
#include <math.h>

#define TSTEPS  2048
#define FDIM    15
#define UD      256
#define NGROUPS 8
#define BG      8      // batch rows per group
#define NSLICE  16
#define NT      384
#define NCTA    (NGROUPS * NSLICE)
#define SP      260    // padded row stride for h state (floats)
#define WS      260    // padded row stride for weights (floats)
#define RB      148    // red: row stride (floats)   (conflict-free for phase3 reads)
#define RKC     1192   // red: kc stride (floats) = 8*148 + 8

typedef unsigned long long u64;

// Double-buffered hidden states (tiny: live in L2)
__device__ float    g_h1[2 * NGROUPS * BG * UD];
__device__ float    g_h2[2 * NGROUPS * BG * UD];
__device__ unsigned g_flags[NCTA];
// Precomputed x@W1 + b1_in, layout [t][cta][b*48+c]  (402 MB)
__device__ float    g_xp[(size_t)TSTEPS * NCTA * 384];

__global__ void init_kernel() {
    if (threadIdx.x < NCTA) g_flags[threadIdx.x] = 0u;
}

// Precompute kernel: xp = x @ W1 + b1_in for every step, permuted per-CTA.
__global__ void __launch_bounds__(NT, 2)
xp_kernel(const float* __restrict__ inp, const float* __restrict__ W1,
          const float* __restrict__ b1)
{
    const int cta = blockIdx.x;
    const int grp = cta >> 4, sl = cta & 15;
    const int t0  = blockIdx.y * 32;
    const int tid = threadIdx.x;
    const int b   = tid / 48, c = tid - b * 48;
    const int col = ((c >> 4) << 8) + (sl << 4) + (c & 15);

    float w[FDIM];
    #pragma unroll
    for (int f = 0; f < FDIM; f++) w[f] = W1[f * 768 + col];
    const float bias = b1[col];
    const float* xrow = inp + (size_t)(grp * BG + b) * (TSTEPS * FDIM);

    for (int t = t0; t < t0 + 32; t++) {
        const float* x = xrow + t * FDIM;
        float acc = bias;
        #pragma unroll
        for (int f = 0; f < FDIM; f++) acc += x[f] * w[f];
        g_xp[((size_t)t * NCTA + cta) * 384 + tid] = acc;
    }
}

__device__ __forceinline__ float sigmoidf_(float x) {
    return __fdividef(1.0f, 1.0f + __expf(-x));
}

// packed f32x2 fma
__device__ __forceinline__ u64 ffma2(u64 a, u64 b, u64 c) {
    u64 d;
    asm("fma.rn.f32x2 %0, %1, %2, %3;" : "=l"(d) : "l"(a), "l"(b), "l"(c));
    return d;
}

// arrive: caller guarantees __syncthreads() before; one thread publishes epoch.
__device__ __forceinline__ void bar_arrive(int grp, int sl, unsigned e) {
    __threadfence();
    ((volatile unsigned*)g_flags)[grp * 16 + sl] = e;
}

// wait: every warp polls all 16 flags of its group.
__device__ __forceinline__ void bar_wait(int grp, unsigned e) {
    const int lane = threadIdx.x & 31;
    for (;;) {
        unsigned v = e;
        if (lane < 16) v = ((volatile unsigned*)g_flags)[grp * 16 + lane];
        if (__all_sync(0xffffffffu, v >= e)) break;
    }
    __threadfence();
}

__global__ void __launch_bounds__(NT, 1)
gru_kernel(const float* __restrict__ inp, const float* __restrict__ W1,
           const float* __restrict__ U1g, const float* __restrict__ b1,
           const float* __restrict__ W2g, const float* __restrict__ U2g,
           const float* __restrict__ b2, float* __restrict__ out)
{
    extern __shared__ float smem[];
    float* sW   = smem;                 // [144][WS]  rows 0..47 U1, 48..95 W2, 96..143 U2 (transposed)
    float* sh1  = sW   + 144 * WS;      // [8][SP]   h1[i-1]
    float* sh2  = sh1  +   8 * SP;      // [8][SP]   h2[i-2]
    float* sxp  = sh2  +   8 * SP;      // [384]     xp1 for this step (b*48+c)
    float* sb   = sxp  + 384;           // [3*48] : b1_rec | b2_in | b2_rec
    float* red  = sb   + 3 * 48;        // [8 kc][8 rows * RB]  k-split partials

    const int tid   = threadIdx.x;
    const int grp   = blockIdx.x >> 4;
    const int sl    = blockIdx.x & 15;
    const int brow0 = grp * BG;
    const int cta   = blockIdx.x;

    // ---- one-time: load weight slices (transposed) into SMEM ----
    for (int idx = tid; idx < 48 * 256; idx += NT) {
        int k = idx / 48, c = idx - k * 48;
        int col = ((c >> 4) << 8) + (sl << 4) + (c & 15);   // gate*256 + slice*16 + u
        sW[c * WS + k]          = U1g[k * 768 + col];
        sW[(48 + c) * WS + k]   = W2g[k * 768 + col];
        sW[(96 + c) * WS + k]   = U2g[k * 768 + col];
    }
    for (int c = tid; c < 48; c += NT) {
        int col = ((c >> 4) << 8) + (sl << 4) + (c & 15);
        sb[c]       = b1[768 + col];   // b1_rec
        sb[48 + c]  = b2[col];         // b2_in
        sb[96 + c]  = b2[768 + col];   // b2_rec
    }
    if (tid < 128) {
        int b = tid & 7, u = tid >> 3;
        int scol = (sl << 4) + u;
        for (int buf = 0; buf < 2; buf++) {
            g_h1[(buf * NGROUPS + grp) * BG * UD + b * UD + scol] = 0.f;
            g_h2[(buf * NGROUPS + grp) * BG * UD + b * UD + scol] = 0.f;
        }
    }

    // thread tile decomposition for the fused GEMM
    const int kc  = tid / 48;          // 0..7  (k chunk of 32)
    const int r48 = tid - kc * 48;
    const int cg  = r48 >> 1;          // 0..23 (6 columns each)
    const int rh  = r48 & 1;           // 0..1  (4 rows each)
    const float* hsel  = (cg < 16 ? sh1 : sh2) + rh * 4 * SP + kc * 32;
    const float* wbase = sW + (cg * 6) * WS + kc * 32;

    __syncthreads();
    if (tid == 0) bar_arrive(grp, sl, 1u);
    bar_wait(grp, 1u);

    for (int i = 0; i <= TSTEPS; ++i) {
        // ---- prefetch xp for this step (independent of barrier) ----
        float xp_pref = 0.f;
        if (i < TSTEPS)
            xp_pref = __ldcg(&g_xp[((size_t)i * NCTA + cta) * 384 + tid]);

        // ---- wait for group to finish iteration i-1 ----
        if (i > 0) bar_wait(grp, (unsigned)(i + 1));

        // ---- phase 1: load shared state (L2-coherent) ----
        const float* gh1 = g_h1 + (((i + 1) & 1) * NGROUPS + grp) * BG * UD;   // h1[i-1]
        const float* gh2 = g_h2 + (((i) & 1)     * NGROUPS + grp) * BG * UD;   // h2[i-2]
        for (int idx = tid; idx < 512; idx += NT) {
            int b = idx >> 6, k4 = idx & 63;
            float4 v1 = __ldcg(((const float4*)(gh1 + b * UD)) + k4);
            float4 v2 = __ldcg(((const float4*)(gh2 + b * UD)) + k4);
            *(float4*)(sh1 + b * SP + (k4 << 2)) = v1;
            *(float4*)(sh2 + b * SP + (k4 << 2)) = v2;
        }
        sxp[tid] = xp_pref;
        __syncthreads();

        // ---- phase 2: fused register-tiled GEMM (packed f32x2 FMA) ----
        // outputs: [8 rows][144 cols]; cols 0..47 rec1, 48..95 xp2, 96..143 rec2
        {
            u64 acc[4][6];
            #pragma unroll
            for (int j = 0; j < 4; j++)
                #pragma unroll
                for (int jj = 0; jj < 6; jj++) acc[j][jj] = 0ull;

            #pragma unroll
            for (int s = 0; s < 8; s++) {
                ulonglong2 h2v[4];
                #pragma unroll
                for (int j = 0; j < 4; j++)
                    h2v[j] = *(const ulonglong2*)(hsel + j * SP + s * 4);
                #pragma unroll
                for (int jj = 0; jj < 6; jj++) {
                    ulonglong2 w2 = *(const ulonglong2*)(wbase + jj * WS + s * 4);
                    #pragma unroll
                    for (int j = 0; j < 4; j++) {
                        acc[j][jj] = ffma2(h2v[j].x, w2.x, acc[j][jj]);
                        acc[j][jj] = ffma2(h2v[j].y, w2.y, acc[j][jj]);
                    }
                }
            }
            // write k-split partials: red[kc][row*RB + col]
            #pragma unroll
            for (int j = 0; j < 4; j++) {
                int row = rh * 4 + j;
                #pragma unroll
                for (int jj = 0; jj < 6; jj += 2) {
                    float2 p0 = *(float2*)&acc[j][jj];
                    float2 p1 = *(float2*)&acc[j][jj + 1];
                    int o = kc * RKC + row * RB + cg * 6 + jj;
                    *(float2*)&red[o] = make_float2(p0.x + p0.y, p1.x + p1.y);
                }
            }
        }
        __syncthreads();

        // ---- phase 3: gates + state update (128 threads: one (b,u) each) ----
        if (tid < 128) {
            int b = tid & 7, u = tid >> 3;
            int scol = (sl << 4) + u;
            int gb = brow0 + b;
            const float* rrow = red + b * RB;

            if (i < TSTEPS) {   // layer 1: h1[i]
                float rec[3];
                #pragma unroll
                for (int gci = 0; gci < 3; gci++) {
                    int c = gci * 16 + u;
                    float s = rrow[c];
                    #pragma unroll
                    for (int k2 = 1; k2 < 8; k2++) s += rrow[k2 * RKC + c];
                    rec[gci] = s + sb[c];                       // + b1_rec
                }
                float z  = sigmoidf_(sxp[b * 48 + u]          + rec[0]);
                float r  = sigmoidf_(sxp[b * 48 + 16 + u]     + rec[1]);
                float hh = fmaxf(0.f, sxp[b * 48 + 32 + u] + r * rec[2]);
                float hp = sh1[b * SP + scol];
                float hn = z * hp + (1.f - z) * hh;
                g_h1[((i & 1) * NGROUPS + grp) * BG * UD + b * UD + scol] = hn;
                if (i == TSTEPS - 1) out[64 * 256 + gb * 256 + scol] = hn;   // state1
            }
            if (i >= 1) {       // layer 2: h2[i-1]
                float xpv[3], rec[3];
                #pragma unroll
                for (int gci = 0; gci < 3; gci++) {
                    int cx = 48 + gci * 16 + u;
                    int cr = 96 + gci * 16 + u;
                    float sx_ = rrow[cx];
                    float sr_ = rrow[cr];
                    #pragma unroll
                    for (int k2 = 1; k2 < 8; k2++) {
                        sx_ += rrow[k2 * RKC + cx];
                        sr_ += rrow[k2 * RKC + cr];
                    }
                    xpv[gci] = sx_ + sb[48 + gci * 16 + u];     // + b2_in
                    rec[gci] = sr_ + sb[96 + gci * 16 + u];     // + b2_rec
                }
                float z  = sigmoidf_(xpv[0] + rec[0]);
                float r  = sigmoidf_(xpv[1] + rec[1]);
                float hh = fmaxf(0.f, xpv[2] + r * rec[2]);
                float hp = sh2[b * SP + scol];
                float hn = z * hp + (1.f - z) * hh;
                g_h2[(((i - 1) & 1) * NGROUPS + grp) * BG * UD + b * UD + scol] = hn;
                if (i == TSTEPS) {
                    out[gb * 256 + scol]                 = hn;   // x = seq2[:, -1, :]
                    out[2 * 64 * 256 + gb * 256 + scol]  = hn;   // state2
                }
            }
        }

        __syncthreads();
        if (tid == 0) bar_arrive(grp, sl, (unsigned)(i + 2));
    }
}

extern "C" void kernel_launch(void* const* d_in, const int* in_sizes, int n_in,
                              void* d_out, int out_size) {
    const float* inp = (const float*)d_in[0];
    const float* W1  = (const float*)d_in[1];
    const float* U1  = (const float*)d_in[2];
    const float* b1  = (const float*)d_in[3];
    const float* W2  = (const float*)d_in[4];
    const float* U2  = (const float*)d_in[5];
    const float* b2  = (const float*)d_in[6];
    float* out = (float*)d_out;

    size_t smem_bytes = (size_t)(144 * WS + 8 * SP + 8 * SP +
                                 384 + 3 * 48 + 8 * RKC) * sizeof(float);
    cudaFuncSetAttribute(gru_kernel, cudaFuncAttributeMaxDynamicSharedMemorySize,
                         (int)smem_bytes);
    init_kernel<<<1, 128>>>();
    xp_kernel<<<dim3(NCTA, TSTEPS / 32), NT>>>(inp, W1, b1);
    gru_kernel<<<NCTA, NT, smem_bytes>>>(inp, W1, U1, b1, W2, U2, b2, out);
}

// round 8
// speedup vs baseline: 2.1822x; 2.1822x over previous
#include <cuda_runtime.h>
#include <math.h>

#define TSTEPS  2048
#define FDIM    15
#define UD      256
#define NGROUPS 8
#define BG      8      // batch rows per group
#define NT      384
#define NCTA    128
#define SP      260    // padded row stride for h state (floats)
#define WS      260    // padded row stride for weights (floats)
#define RB1     52     // red1 row stride
#define RKC1    (8 * RB1)
#define RB2     100    // red2 row stride
#define RKC2    (8 * RB2)

typedef unsigned long long u64;

// Double-buffered hidden states (tiny: live in L2)
__device__ float    g_h1[2 * NGROUPS * BG * UD];
__device__ float    g_h2[2 * NGROUPS * BG * UD];
__device__ unsigned g_c1[NGROUPS];
__device__ unsigned g_c2[NGROUPS];

__global__ void init_kernel() {
    if (threadIdx.x < NGROUPS) {
        g_c1[threadIdx.x] = 0u;
        g_c2[threadIdx.x] = 0u;
    }
}

__device__ __forceinline__ float sigmoidf_(float x) {
    return __fdividef(1.0f, 1.0f + __expf(-x));
}

// packed f32x2 fma
__device__ __forceinline__ u64 ffma2(u64 a, u64 b, u64 c) {
    u64 d;
    asm("fma.rn.f32x2 %0, %1, %2, %3;" : "=l"(d) : "l"(a), "l"(b), "l"(c));
    return d;
}

// release-arrive: block-wide sync, then tid0 fences + bumps counter
__device__ __forceinline__ void bar_arrive(unsigned* cnt) {
    __syncthreads();
    if (threadIdx.x == 0) {
        __threadfence();
        atomicAdd(cnt, 1u);
    }
}
// acquire-wait: tid0 spins, then broadcast
__device__ __forceinline__ void bar_wait(unsigned* cnt, unsigned target) {
    __syncthreads();
    if (threadIdx.x == 0) {
        while (*((volatile unsigned*)cnt) < target) { }
        __threadfence();
    }
    __syncthreads();
}

__global__ void __launch_bounds__(NT, 1)
gru_kernel(const float* __restrict__ inp, const float* __restrict__ W1,
           const float* __restrict__ U1g, const float* __restrict__ b1,
           const float* __restrict__ W2g, const float* __restrict__ U2g,
           const float* __restrict__ b2, float* __restrict__ out)
{
    extern __shared__ float smem[];
    float* sW   = smem;                 // [144][WS] rows: 0..47 U1, 48..95 W2, 96..143 U2 (transposed)
    float* sh1  = sW   + 144 * WS;      // [8][SP]   h1[i-1]
    float* sh2  = sh1  +   8 * SP;      // [8][SP]   h2[i-2]
    float* sW1t = sh2  +   8 * SP;      // [48][16]
    float* sx   = sW1t +  48 * 16;      // [8][16]
    float* sb   = sx   +   8 * 16;      // [4*48]: b1_in | b1_rec | b2_in | b2_rec
    float* red1 = sb   +   4 * 48;      // [8][RKC1]
    float* red2 = red1 +   8 * RKC1;    // [8][RKC2]

    const int tid   = threadIdx.x;
    const int grp   = blockIdx.x >> 4;
    const int sl    = blockIdx.x & 15;
    const int brow0 = grp * BG;

    // ---- one-time: load weight slices (transposed) into SMEM ----
    for (int idx = tid; idx < 48 * 256; idx += NT) {
        int k = idx / 48, c = idx - k * 48;
        int col = ((c >> 4) << 8) + (sl << 4) + (c & 15);   // gate*256 + slice*16 + u
        sW[c * WS + k]          = U1g[k * 768 + col];
        sW[(48 + c) * WS + k]   = W2g[k * 768 + col];
        sW[(96 + c) * WS + k]   = U2g[k * 768 + col];
    }
    for (int idx = tid; idx < 48 * 15; idx += NT) {
        int f = idx / 48, c = idx - f * 48;
        int col = ((c >> 4) << 8) + (sl << 4) + (c & 15);
        sW1t[c * 16 + f] = W1[f * 768 + col];
    }
    for (int c = tid; c < 48; c += NT) {
        int col = ((c >> 4) << 8) + (sl << 4) + (c & 15);
        sb[c]        = b1[col];        // b1_in
        sb[48 + c]   = b1[768 + col];  // b1_rec
        sb[96 + c]   = b2[col];        // b2_in
        sb[144 + c]  = b2[768 + col];  // b2_rec
    }
    if (tid < 128) {
        int b = tid & 7, u = tid >> 3;
        int scol = (sl << 4) + u;
        for (int buf = 0; buf < 2; buf++) {
            g_h1[(buf * NGROUPS + grp) * BG * UD + b * UD + scol] = 0.f;
            g_h2[(buf * NGROUPS + grp) * BG * UD + b * UD + scol] = 0.f;
        }
    }

    // thread tile decomposition: kc (k-chunk of 32) x cg x rh
    const int kc  = tid / 48;          // 0..7
    const int r48 = tid - kc * 48;
    const int cg  = r48 >> 1;          // 0..23
    const int rh  = r48 & 1;           // 0..1 (4 rows each)
    const float* hA  = sh1 + rh * 4 * SP + kc * 32;
    const float* hB2 = sh2 + rh * 4 * SP + kc * 32;
    const float* wA  = sW + cg * WS + kc * 32;            // U1 rows cg, cg+24
    const float* wB  = sW + (48 + cg) * WS + kc * 32;     // W2/U2 rows 48+cg+24*jj

    // initial barrier: zeros + weights visible group-wide
    bar_arrive(&g_c1[grp]);
    bar_arrive(&g_c2[grp]);
    bar_wait(&g_c1[grp], 16u);
    bar_wait(&g_c2[grp], 16u);

    const int b15 = tid / 15, f15 = tid - b15 * 15;  // input-load map (tid<120)

    for (int i = 0; i <= TSTEPS; ++i) {
        // ---- prefetch input row i into registers (independent of barrier) ----
        float xin = 0.f;
        if (i < TSTEPS && tid < 120)
            xin = __ldg(&inp[(size_t)(brow0 + b15) * (TSTEPS * FDIM) + i * FDIM + f15]);

        // ================= PHASE A : layer-1 critical path =================
        bar_wait(&g_c1[grp], 16u * (unsigned)(i + 1));

        // load h1[i-1] from buf ((i+1)&1)  -- 8 rows x 64 float4
        {
            const float* gh1 = g_h1 + (((i + 1) & 1) * NGROUPS + grp) * BG * UD;
            for (int idx = tid; idx < 512; idx += NT) {
                int b = idx >> 6, k4 = idx & 63;
                float4 v = __ldcg(((const float4*)(gh1 + b * UD)) + k4);
                *(float4*)(sh1 + b * SP + (k4 << 2)) = v;
            }
            if (i < TSTEPS && tid < 120) sx[b15 * 16 + f15] = xin;
        }
        __syncthreads();

        if (i < TSTEPS) {
            // GEMM A: rec1 = h1[i-1] @ U1slice  (8 x 48 x 256), cols {cg, cg+24}
            u64 acc[4][2];
            #pragma unroll
            for (int j = 0; j < 4; j++) { acc[j][0] = 0ull; acc[j][1] = 0ull; }
            #pragma unroll
            for (int s = 0; s < 8; s++) {
                ulonglong2 hv[4];
                #pragma unroll
                for (int j = 0; j < 4; j++)
                    hv[j] = *(const ulonglong2*)(hA + j * SP + s * 4);
                #pragma unroll
                for (int jj = 0; jj < 2; jj++) {
                    ulonglong2 w2 = *(const ulonglong2*)(wA + jj * 24 * WS + s * 4);
                    #pragma unroll
                    for (int j = 0; j < 4; j++) {
                        acc[j][jj] = ffma2(hv[j].x, w2.x, acc[j][jj]);
                        acc[j][jj] = ffma2(hv[j].y, w2.y, acc[j][jj]);
                    }
                }
            }
            #pragma unroll
            for (int j = 0; j < 4; j++) {
                int row = rh * 4 + j;
                #pragma unroll
                for (int jj = 0; jj < 2; jj++) {
                    float2 p = *(float2*)&acc[j][jj];
                    red1[kc * RKC1 + row * RB1 + cg + 24 * jj] = p.x + p.y;
                }
            }
        }
        __syncthreads();

        if (i < TSTEPS && tid < 128) {
            int b = tid & 7, u = tid >> 3;
            int scol = (sl << 4) + u;
            const float* rrow = red1 + b * RB1;
            float rec[3], xp[3];
            #pragma unroll
            for (int g = 0; g < 3; g++) {
                int c = g * 16 + u;
                float s = rrow[c];
                #pragma unroll
                for (int k2 = 1; k2 < 8; k2++) s += rrow[k2 * RKC1 + c];
                rec[g] = s + sb[48 + c];                 // + b1_rec
                float a = sb[c];                         // b1_in
                const float* wr = sW1t + c * 16;
                const float* xr = sx + b * 16;
                #pragma unroll
                for (int f = 0; f < 15; f++) a += xr[f] * wr[f];
                xp[g] = a;
            }
            float z  = sigmoidf_(xp[0] + rec[0]);
            float r  = sigmoidf_(xp[1] + rec[1]);
            float hh = fmaxf(0.f, xp[2] + r * rec[2]);
            float hp = sh1[b * SP + scol];
            float hn = z * hp + (1.f - z) * hh;
            g_h1[((i & 1) * NGROUPS + grp) * BG * UD + b * UD + scol] = hn;
            if (i == TSTEPS - 1) out[64 * 256 + (brow0 + b) * 256 + scol] = hn;  // state1
        }
        if (i < TSTEPS) bar_arrive(&g_c1[grp]);

        // ================= PHASE B : layer-2 (hides barrier) =================
        if (i >= 1) {
            bar_wait(&g_c2[grp], 16u * (unsigned)i);

            // load h2[i-2] from buf (i&1)  -- 8 rows x 64 float4
            {
                const float* gh2 = g_h2 + ((i & 1) * NGROUPS + grp) * BG * UD;
                for (int idx = tid; idx < 512; idx += NT) {
                    int b = idx >> 6, k4 = idx & 63;
                    float4 v = __ldcg(((const float4*)(gh2 + b * UD)) + k4);
                    *(float4*)(sh2 + b * SP + (k4 << 2)) = v;
                }
            }
            __syncthreads();

            // GEMM B: [xp2 | rec2] (8 x 96 x 256); cols c = cg + 24*jj, jj<2 -> h1, jj>=2 -> h2
            {
                u64 acc[4][4];
                #pragma unroll
                for (int j = 0; j < 4; j++)
                    #pragma unroll
                    for (int jj = 0; jj < 4; jj++) acc[j][jj] = 0ull;
                #pragma unroll
                for (int s = 0; s < 8; s++) {
                    ulonglong2 h1v[4], h2v[4];
                    #pragma unroll
                    for (int j = 0; j < 4; j++) {
                        h1v[j] = *(const ulonglong2*)(hA  + j * SP + s * 4);
                        h2v[j] = *(const ulonglong2*)(hB2 + j * SP + s * 4);
                    }
                    #pragma unroll
                    for (int jj = 0; jj < 4; jj++) {
                        ulonglong2 w2 = *(const ulonglong2*)(wB + jj * 24 * WS + s * 4);
                        #pragma unroll
                        for (int j = 0; j < 4; j++) {
                            ulonglong2 hv = (jj < 2) ? h1v[j] : h2v[j];
                            acc[j][jj] = ffma2(hv.x, w2.x, acc[j][jj]);
                            acc[j][jj] = ffma2(hv.y, w2.y, acc[j][jj]);
                        }
                    }
                }
                #pragma unroll
                for (int j = 0; j < 4; j++) {
                    int row = rh * 4 + j;
                    #pragma unroll
                    for (int jj = 0; jj < 4; jj++) {
                        float2 p = *(float2*)&acc[j][jj];
                        red2[kc * RKC2 + row * RB2 + cg + 24 * jj] = p.x + p.y;
                    }
                }
            }
            __syncthreads();

            if (tid < 128) {
                int b = tid & 7, u = tid >> 3;
                int scol = (sl << 4) + u;
                int gb = brow0 + b;
                const float* rrow = red2 + b * RB2;
                float xpv[3], rec[3];
                #pragma unroll
                for (int g = 0; g < 3; g++) {
                    int cx = g * 16 + u;
                    int cr = 48 + g * 16 + u;
                    float sx_ = rrow[cx];
                    float sr_ = rrow[cr];
                    #pragma unroll
                    for (int k2 = 1; k2 < 8; k2++) {
                        sx_ += rrow[k2 * RKC2 + cx];
                        sr_ += rrow[k2 * RKC2 + cr];
                    }
                    xpv[g] = sx_ + sb[96 + g * 16 + u];   // + b2_in
                    rec[g] = sr_ + sb[144 + g * 16 + u];  // + b2_rec
                }
                float z  = sigmoidf_(xpv[0] + rec[0]);
                float r  = sigmoidf_(xpv[1] + rec[1]);
                float hh = fmaxf(0.f, xpv[2] + r * rec[2]);
                float hp = sh2[b * SP + scol];
                float hn = z * hp + (1.f - z) * hh;
                g_h2[((((i - 1) & 1)) * NGROUPS + grp) * BG * UD + b * UD + scol] = hn;
                if (i == TSTEPS) {
                    out[gb * 256 + scol]                = hn;   // x = seq2[:, -1, :]
                    out[2 * 64 * 256 + gb * 256 + scol] = hn;   // state2
                }
            }
            bar_arrive(&g_c2[grp]);
        }
    }
}

extern "C" void kernel_launch(void* const* d_in, const int* in_sizes, int n_in,
                              void* d_out, int out_size) {
    const float* inp = (const float*)d_in[0];
    const float* W1  = (const float*)d_in[1];
    const float* U1  = (const float*)d_in[2];
    const float* b1  = (const float*)d_in[3];
    const float* W2  = (const float*)d_in[4];
    const float* U2  = (const float*)d_in[5];
    const float* b2  = (const float*)d_in[6];
    float* out = (float*)d_out;

    size_t smem_bytes = (size_t)(144 * WS + 8 * SP + 8 * SP +
                                 48 * 16 + 8 * 16 + 4 * 48 +
                                 8 * RKC1 + 8 * RKC2) * sizeof(float);
    cudaFuncSetAttribute(gru_kernel, cudaFuncAttributeMaxDynamicSharedMemorySize,
                         (int)smem_bytes);
    init_kernel<<<1, 32>>>();
    gru_kernel<<<NCTA, NT, smem_bytes>>>(inp, W1, U1, b1, W2, U2, b2, out);
}